// round 14
// baseline (speedup 1.0000x reference)
#include <cuda_runtime.h>
#include <cstdint>

// ============================================================================
// Layer_70411693850653 — equivariant GNN layer. (R13 + TILE=16, pad-free MMA)
//
//  * messages[384:640] never consumed -> skipped
//  * agg == 1.5 * feats[:, :128] -> skip connection folded into weights
//  * scatter_mean via bucketed inverse-CSR + register gather (no float atomics)
//  * Phase B = tf32 mma.sync.m16n8k8: sF row-major [64 x 100], 4 M-tiles
//    (scalar/x/y/z) x 2 n-halves = 8 warps, ZERO pad rows -> 12 MMA/node
//  * NO cross-barrier prefetch (twice-measured regression)
//  * TILE=16, 51.2KB dynamic smem, 4 blocks/SM
// ============================================================================

#define N_MAX 50000
#define CAP   32
#define TILE  16
#define FSP   100        // row stride words: bank=(4r+c+8k)%32 -> conflict-free
#define NBLK  592        // 4 per SM on 148 SMs
#define SMEM_BYTES ((64 * FSP + 2 * 32 * FSP) * 4)   // 51200

__device__ int  g_deg[N_MAX];            // zero-init at load; k_main resets
__device__ int2 g_bucket[N_MAX * CAP];   // {sender, edge}

// ---------------------------------------------------------------------------
__global__ void k_fill(const int* __restrict__ recv,
                       const int* __restrict__ senders, int E) {
    int e = blockIdx.x * blockDim.x + threadIdx.x;
    if (e < E) {
        int r = recv[e];
        int slot = atomicAdd(&g_deg[r], 1);
        if (slot < CAP) g_bucket[r * CAP + slot] = make_int2(senders[e], e);
    }
}

// ---------------------------------------------------------------------------
__device__ __forceinline__ uint32_t f2tf(float x) {
    uint32_t r;
    asm("cvt.rna.tf32.f32 %0, %1;" : "=r"(r) : "f"(x));
    return r;
}

__device__ __forceinline__ void mma_tf32(float c[4],
    uint32_t a0, uint32_t a1, uint32_t a2, uint32_t a3,
    uint32_t b0, uint32_t b1)
{
    asm volatile(
        "mma.sync.aligned.m16n8k8.row.col.f32.tf32.tf32.f32 "
        "{%0,%1,%2,%3}, {%4,%5,%6,%7}, {%8,%9}, {%0,%1,%2,%3};"
        : "+f"(c[0]), "+f"(c[1]), "+f"(c[2]), "+f"(c[3])
        : "r"(a0), "r"(a1), "r"(a2), "r"(a3), "r"(b0), "r"(b1));
}

// ---------------------------------------------------------------------------
__global__ void __launch_bounds__(256, 4) k_main(
    const float* __restrict__ nf, const float* __restrict__ sh,
    const float* __restrict__ W0, const float* __restrict__ W1,
    const float* __restrict__ Ws0, const float* __restrict__ Ws1,
    float* __restrict__ out, int N)
{
    extern __shared__ uint32_t smem[];
    uint32_t* sF  = smem;                    // [64 * FSP] tf32 feats
    uint32_t* sW0 = smem + 64 * FSP;         // [32 * FSP] Wt0[v][u] tf32
    uint32_t* sW1 = sW0 + 32 * FSP;          // [32 * FSP] Wt1[v][u] tf32

    const float invA = 0.10206207261596575f;         // 1/sqrt(96)
    const float cB   = 1.5f * 0.17677669529663687f;  // 1.5/sqrt(32)
    const float INV_SQRT3 = 0.5773502691896258f;

    const int t    = threadIdx.x;
    const int w    = t >> 5;
    const int lane = t & 31;

    // ---- prologue: effective weights, transposed to [v][u], tf32 ----------
    for (int i = t; i < 96 * 32; i += 256) {
        int u = i >> 5, v = i & 31;
        float w0 = W0[i] * invA;
        float w1 = W1[i] * invA;
        if (u < 32) { w0 = fmaf(cB, Ws0[i], w0); w1 = fmaf(cB, Ws1[i], w1); }
        sW0[v * FSP + u] = f2tf(w0);
        sW1[v * FSP + u] = f2tf(w1);
    }

    // fragment indices (loop-invariant)
    const int r0 = lane >> 2;   // 0..7
    const int c0 = lane & 3;    // 0..3
    // Phase B role: warp w = (Mtile m, n-half nh); m: 0=scalar,1=x,2=y,3=z
    const int m  = w >> 1;
    const int nh = w & 1;
    const int mbase = m * 16;
    const int nbase = nh * 16;
    const uint32_t* Wt = (m == 0) ? sW0 : sW1;
    const int cc = m - 1;

    const int ntiles = (N + TILE - 1) / TILE;
    for (int tile = blockIdx.x; tile < ntiles; tile += gridDim.x) {
        __syncthreads();   // previous tile's Phase B readers done with sF

        // ---------------- Phase A: 2 nodes per warp ------------------------
        #pragma unroll
        for (int half = 0; half < 2; half++) {
            const int ni = half * 8 + w;
            const int n  = tile * TILE + ni;

            float a0 = 0.f, ax = 0.f, ay = 0.f, az = 0.f;
            float p00 = 0.f, dot = 0.f;
            float qx = 0.f, qy = 0.f, qz = 0.f;   // p01 = s0*f1
            float rx = 0.f, ry = 0.f, rz = 0.f;   // p10 = f0*s1

            int d = 0;
            if (n < N) d = g_deg[n];
            const int dc = min(d, CAP);
            if (n < N && lane == 0) g_deg[n] = 0;   // maintain zero-invariant

            int    my_s  = 0;
            float4 my_sh = make_float4(0.f, 0.f, 0.f, 0.f);
            if (lane < dc) {
                int2 se = g_bucket[n * CAP + lane];
                my_s    = se.x;
                my_sh   = *reinterpret_cast<const float4*>(sh + (size_t)se.y * 4);
            }

            for (int j = 0; j < dc; j++) {
                int   s   = __shfl_sync(0xffffffffu, my_s,    j);
                float s0  = __shfl_sync(0xffffffffu, my_sh.x, j);
                float s1x = __shfl_sync(0xffffffffu, my_sh.y, j);
                float s1y = __shfl_sync(0xffffffffu, my_sh.z, j);
                float s1z = __shfl_sync(0xffffffffu, my_sh.w, j);

                const float* row = nf + (size_t)s * 128;
                float f0 = row[lane];
                float g0 = row[32 + 3 * lane];
                float g1 = row[33 + 3 * lane];
                float g2 = row[34 + 3 * lane];

                a0 += f0; ax += g0; ay += g1; az += g2;
                p00 = fmaf(s0, f0, p00);
                dot = fmaf(s1x, g0, fmaf(s1y, g1, fmaf(s1z, g2, dot)));
                qx  = fmaf(s0, g0, qx);
                qy  = fmaf(s0, g1, qy);
                qz  = fmaf(s0, g2, qz);
                rx  = fmaf(f0, s1x, rx);
                ry  = fmaf(f0, s1y, ry);
                rz  = fmaf(f0, s1z, rz);
            }

            const float scale = 1.0f / (1.5f * (float)max(d, 1));
            // scalar row ni:      [a0, p00, dot]
            sF[ ni       * FSP +      lane] = f2tf(a0 * scale);
            sF[ ni       * FSP + 32 + lane] = f2tf(p00 * scale);
            sF[ ni       * FSP + 64 + lane] = f2tf(dot * scale * INV_SQRT3);
            // x row 16+ni:        [ax, qx, rx]
            sF[(16 + ni) * FSP +      lane] = f2tf(ax * scale);
            sF[(16 + ni) * FSP + 32 + lane] = f2tf(qx * scale);
            sF[(16 + ni) * FSP + 64 + lane] = f2tf(rx * scale);
            // y row 32+ni:        [ay, qy, ry]
            sF[(32 + ni) * FSP +      lane] = f2tf(ay * scale);
            sF[(32 + ni) * FSP + 32 + lane] = f2tf(qy * scale);
            sF[(32 + ni) * FSP + 64 + lane] = f2tf(ry * scale);
            // z row 48+ni:        [az, qz, rz]
            sF[(48 + ni) * FSP +      lane] = f2tf(az * scale);
            sF[(48 + ni) * FSP + 32 + lane] = f2tf(qz * scale);
            sF[(48 + ni) * FSP + 64 + lane] = f2tf(rz * scale);
        }
        __syncthreads();   // sF ready

        // ---------------- Phase B: tf32 MMA, all 8 warps --------------------
        {
            float c[2][4];
            #pragma unroll
            for (int nt = 0; nt < 2; nt++)
                #pragma unroll
                for (int i = 0; i < 4; i++) c[nt][i] = 0.f;

            #pragma unroll
            for (int k = 0; k < 12; k++) {
                const int kb = 8 * k;
                uint32_t a0 = sF[(mbase + r0)     * FSP + kb + c0];
                uint32_t a1 = sF[(mbase + r0 + 8) * FSP + kb + c0];
                uint32_t a2 = sF[(mbase + r0)     * FSP + kb + c0 + 4];
                uint32_t a3 = sF[(mbase + r0 + 8) * FSP + kb + c0 + 4];
                #pragma unroll
                for (int nt = 0; nt < 2; nt++) {
                    const int nb = nbase + nt * 8;
                    uint32_t b0 = Wt[(nb + r0) * FSP + kb + c0];
                    uint32_t b1 = Wt[(nb + r0) * FSP + kb + c0 + 4];
                    mma_tf32(c[nt], a0, a1, a2, a3, b0, b1);
                }
            }

            // store: C rows r0 -> node_lo, r0+8 -> node_hi (all real rows)
            const int node_lo = tile * TILE + r0;
            const int node_hi = node_lo + 8;
            float* olo = out + (size_t)node_lo * 128;
            float* ohi = out + (size_t)node_hi * 128;
            #pragma unroll
            for (int nt = 0; nt < 2; nt++) {
                int v0 = nbase + nt * 8 + 2 * c0;
                if (m == 0) {
                    if (node_lo < N) { olo[v0] = c[nt][0]; olo[v0 + 1] = c[nt][1]; }
                    if (node_hi < N) { ohi[v0] = c[nt][2]; ohi[v0 + 1] = c[nt][3]; }
                } else {
                    if (node_lo < N) {
                        olo[32 + 3 * v0 + cc]       = c[nt][0];
                        olo[32 + 3 * (v0 + 1) + cc] = c[nt][1];
                    }
                    if (node_hi < N) {
                        ohi[32 + 3 * v0 + cc]       = c[nt][2];
                        ohi[32 + 3 * (v0 + 1) + cc] = c[nt][3];
                    }
                }
            }
        }
    }
}

// ---------------------------------------------------------------------------
extern "C" void kernel_launch(void* const* d_in, const int* in_sizes, int n_in,
                              void* d_out, int out_size)
{
    const float* nf       = (const float*)d_in[0];
    const float* sh       = (const float*)d_in[1];
    const int*   senders  = (const int*)  d_in[2];
    const int*   recv     = (const int*)  d_in[3];
    const float* W0       = (const float*)d_in[4];
    const float* W1       = (const float*)d_in[5];
    const float* Ws0      = (const float*)d_in[6];
    const float* Ws1      = (const float*)d_in[7];
    float* out = (float*)d_out;

    int N = in_sizes[0] / 128;
    int E = in_sizes[2];

    cudaFuncSetAttribute(k_main, cudaFuncAttributeMaxDynamicSharedMemorySize,
                         SMEM_BYTES);   // host-side, idempotent, capture-safe

    k_fill<<<(E + 511) / 512, 512>>>(recv, senders, E);
    k_main<<<NBLK, 256, SMEM_BYTES>>>(nf, sh, W0, W1, Ws0, Ws1, out, N);
}

// round 15
// speedup vs baseline: 1.7400x; 1.7400x over previous
#include <cuda_runtime.h>
#include <cstdint>

// ============================================================================
// Layer_70411693850653 — equivariant GNN layer. (R13 + pipelined Phase A)
//
//  * messages[384:640] never consumed -> skipped
//  * agg == 1.5 * feats[:, :128] -> skip connection folded into weights
//  * scatter_mean via bucketed inverse-CSR + register gather (no float atomics)
//  * Phase B = tf32 mma.sync.m16n8k8 (R13 layout, verified): sF [48 x 100],
//    3 M-tiles x 2 n-halves, weights tf32-transposed in smem
//  * R15: depth-2 software pipeline INSIDE Phase A's edge loop (prefetch next
//    edge's sender row before consuming current FMAs) -> MLP 1 -> 2
//  * NO cross-barrier prefetch (twice-measured regression)
//  * TILE=8, 44.8KB smem, 5 blocks/SM
// ============================================================================

#define N_MAX 50000
#define CAP   32
#define TILE  8
#define FSP   100        // row stride (words): banks (4*r0+c0)%32 = permutation
#define NROW  48
#define NBLK  740        // 5 per SM on 148 SMs

__device__ int  g_deg[N_MAX];            // zero-init at load; k_main resets
__device__ int2 g_bucket[N_MAX * CAP];   // {sender, edge}

// ---------------------------------------------------------------------------
__global__ void k_fill(const int* __restrict__ recv,
                       const int* __restrict__ senders, int E) {
    int e = blockIdx.x * blockDim.x + threadIdx.x;
    if (e < E) {
        int r = recv[e];
        int slot = atomicAdd(&g_deg[r], 1);
        if (slot < CAP) g_bucket[r * CAP + slot] = make_int2(senders[e], e);
    }
}

// ---------------------------------------------------------------------------
__device__ __forceinline__ uint32_t f2tf(float x) {
    uint32_t r;
    asm("cvt.rna.tf32.f32 %0, %1;" : "=r"(r) : "f"(x));
    return r;
}

__device__ __forceinline__ void mma_tf32(float c[4],
    uint32_t a0, uint32_t a1, uint32_t a2, uint32_t a3,
    uint32_t b0, uint32_t b1)
{
    asm volatile(
        "mma.sync.aligned.m16n8k8.row.col.f32.tf32.tf32.f32 "
        "{%0,%1,%2,%3}, {%4,%5,%6,%7}, {%8,%9}, {%0,%1,%2,%3};"
        : "+f"(c[0]), "+f"(c[1]), "+f"(c[2]), "+f"(c[3])
        : "r"(a0), "r"(a1), "r"(a2), "r"(a3), "r"(b0), "r"(b1));
}

// ---------------------------------------------------------------------------
__global__ void __launch_bounds__(256, 5) k_main(
    const float* __restrict__ nf, const float* __restrict__ sh,
    const float* __restrict__ W0, const float* __restrict__ W1,
    const float* __restrict__ Ws0, const float* __restrict__ Ws1,
    float* __restrict__ out, int N)
{
    __shared__ uint32_t sF [NROW * FSP];     // tf32 feats rows   (19.2 KB)
    __shared__ uint32_t sW0[32 * FSP];       // Wt0[v][u] tf32    (12.8 KB)
    __shared__ uint32_t sW1[32 * FSP];       // Wt1[v][u] tf32    (12.8 KB)

    const float invA = 0.10206207261596575f;         // 1/sqrt(96)
    const float cB   = 1.5f * 0.17677669529663687f;  // 1.5/sqrt(32)
    const float INV_SQRT3 = 0.5773502691896258f;

    const int t    = threadIdx.x;
    const int w    = t >> 5;
    const int lane = t & 31;

    // ---- prologue: effective weights, transposed to [v][u], tf32 ----------
    for (int i = t; i < 96 * 32; i += 256) {
        int u = i >> 5, v = i & 31;
        float w0 = W0[i] * invA;
        float w1 = W1[i] * invA;
        if (u < 32) { w0 = fmaf(cB, Ws0[i], w0); w1 = fmaf(cB, Ws1[i], w1); }
        sW0[v * FSP + u] = f2tf(w0);
        sW1[v * FSP + u] = f2tf(w1);
    }
    // zero the pad rows (8-15, 40-47) once
    for (int i = t; i < 8 * FSP; i += 256) {
        sF[(8  + i / FSP) * FSP + (i % FSP)] = 0;
        sF[(40 + i / FSP) * FSP + (i % FSP)] = 0;
    }

    // fragment indices (loop-invariant)
    const int r0 = lane >> 2;   // 0..7
    const int c0 = lane & 3;    // 0..3
    // Phase B role: warps 0..5 = (Mtile m, n-half nh); warps 6,7 idle in B
    const int m  = w >> 1;                  // 0,1,2 for w<6
    const int nh = w & 1;
    const int mbase = m * 16;
    const int nbase = nh * 16;
    const uint32_t* Wt = (m == 0) ? sW0 : sW1;

    const int ntiles = (N + TILE - 1) / TILE;
    for (int tile = blockIdx.x; tile < ntiles; tile += gridDim.x) {
        __syncthreads();   // previous tile's Phase B readers done with sF

        // ---------------- Phase A: warp w owns node tile*8 + w -------------
        {
            const int n = tile * TILE + w;

            float a0 = 0.f, ax = 0.f, ay = 0.f, az = 0.f;
            float p00 = 0.f, dot = 0.f;
            float qx = 0.f, qy = 0.f, qz = 0.f;   // p01 = s0*f1
            float rx = 0.f, ry = 0.f, rz = 0.f;   // p10 = f0*s1

            int d = 0;
            if (n < N) d = g_deg[n];
            const int dc = min(d, CAP);
            if (n < N && lane == 0) g_deg[n] = 0;   // maintain zero-invariant

            int    my_s  = 0;
            float4 my_sh = make_float4(0.f, 0.f, 0.f, 0.f);
            if (lane < dc) {
                int2 se = g_bucket[n * CAP + lane];
                my_s    = se.x;
                my_sh   = *reinterpret_cast<const float4*>(sh + (size_t)se.y * 4);
            }

            if (dc > 0) {
                // ---- depth-2 pipelined edge loop (MLP=2) ----
                int s0i = __shfl_sync(0xffffffffu, my_s, 0);
                const float* row0 = nf + (size_t)s0i * 128;
                float f0 = row0[lane];
                float g0 = row0[32 + 3 * lane];
                float g1 = row0[33 + 3 * lane];
                float g2 = row0[34 + 3 * lane];

                for (int j = 0; j < dc; j++) {
                    // prefetch next edge's row BEFORE consuming current
                    float nf0 = 0.f, ng0 = 0.f, ng1 = 0.f, ng2 = 0.f;
                    if (j + 1 < dc) {
                        int sn = __shfl_sync(0xffffffffu, my_s, j + 1);
                        const float* rn = nf + (size_t)sn * 128;
                        nf0 = rn[lane];
                        ng0 = rn[32 + 3 * lane];
                        ng1 = rn[33 + 3 * lane];
                        ng2 = rn[34 + 3 * lane];
                    }
                    // sh components via shfl (register-only, cheap)
                    float s0  = __shfl_sync(0xffffffffu, my_sh.x, j);
                    float s1x = __shfl_sync(0xffffffffu, my_sh.y, j);
                    float s1y = __shfl_sync(0xffffffffu, my_sh.z, j);
                    float s1z = __shfl_sync(0xffffffffu, my_sh.w, j);

                    a0 += f0; ax += g0; ay += g1; az += g2;
                    p00 = fmaf(s0, f0, p00);
                    dot = fmaf(s1x, g0, fmaf(s1y, g1, fmaf(s1z, g2, dot)));
                    qx  = fmaf(s0, g0, qx);
                    qy  = fmaf(s0, g1, qy);
                    qz  = fmaf(s0, g2, qz);
                    rx  = fmaf(f0, s1x, rx);
                    ry  = fmaf(f0, s1y, ry);
                    rz  = fmaf(f0, s1z, rz);

                    f0 = nf0; g0 = ng0; g1 = ng1; g2 = ng2;
                }
            }

            const float scale = 1.0f / (1.5f * (float)max(d, 1));
            // scalar row w:            [a0, p00, dot]
            sF[ w       * FSP +      lane] = f2tf(a0 * scale);
            sF[ w       * FSP + 32 + lane] = f2tf(p00 * scale);
            sF[ w       * FSP + 64 + lane] = f2tf(dot * scale * INV_SQRT3);
            // x row 16+w:              [ax, qx, rx]
            sF[(16 + w) * FSP +      lane] = f2tf(ax * scale);
            sF[(16 + w) * FSP + 32 + lane] = f2tf(qx * scale);
            sF[(16 + w) * FSP + 64 + lane] = f2tf(rx * scale);
            // y row 24+w:              [ay, qy, ry]
            sF[(24 + w) * FSP +      lane] = f2tf(ay * scale);
            sF[(24 + w) * FSP + 32 + lane] = f2tf(qy * scale);
            sF[(24 + w) * FSP + 64 + lane] = f2tf(ry * scale);
            // z row 32+w:              [az, qz, rz]
            sF[(32 + w) * FSP +      lane] = f2tf(az * scale);
            sF[(32 + w) * FSP + 32 + lane] = f2tf(qz * scale);
            sF[(32 + w) * FSP + 64 + lane] = f2tf(rz * scale);
        }
        __syncthreads();   // sF ready

        // ---------------- Phase B: tf32 MMA, warps 0..5 --------------------
        if (w < 6) {
            float c[2][4];
            #pragma unroll
            for (int nt = 0; nt < 2; nt++)
                #pragma unroll
                for (int i = 0; i < 4; i++) c[nt][i] = 0.f;

            #pragma unroll
            for (int k = 0; k < 12; k++) {
                const int kb = 8 * k;
                uint32_t a0 = sF[(mbase + r0)     * FSP + kb + c0];
                uint32_t a1 = sF[(mbase + r0 + 8) * FSP + kb + c0];
                uint32_t a2 = sF[(mbase + r0)     * FSP + kb + c0 + 4];
                uint32_t a3 = sF[(mbase + r0 + 8) * FSP + kb + c0 + 4];
                #pragma unroll
                for (int nt = 0; nt < 2; nt++) {
                    const int nb = nbase + nt * 8;
                    uint32_t b0 = Wt[(nb + r0) * FSP + kb + c0];
                    uint32_t b1 = Wt[(nb + r0) * FSP + kb + c0 + 4];
                    mma_tf32(c[nt], a0, a1, a2, a3, b0, b1);
                }
            }

            // store: C rows r0 (low) / r0+8 (high); pad rows skipped
            const int node = tile * TILE + r0;
            if (node < N) {
                float* o = out + (size_t)node * 128;
                #pragma unroll
                for (int nt = 0; nt < 2; nt++) {
                    int v0 = nbase + nt * 8 + 2 * c0;
                    if (m == 0) {            // scalar (low rows only)
                        o[v0]     = c[nt][0];
                        o[v0 + 1] = c[nt][1];
                    } else if (m == 1) {     // low = x, high = y
                        o[32 + 3 * v0 + 0]       = c[nt][0];
                        o[32 + 3 * (v0 + 1) + 0] = c[nt][1];
                        o[32 + 3 * v0 + 1]       = c[nt][2];
                        o[32 + 3 * (v0 + 1) + 1] = c[nt][3];
                    } else {                 // low = z (high rows are pad)
                        o[32 + 3 * v0 + 2]       = c[nt][0];
                        o[32 + 3 * (v0 + 1) + 2] = c[nt][1];
                    }
                }
            }
        }
    }
}

// ---------------------------------------------------------------------------
extern "C" void kernel_launch(void* const* d_in, const int* in_sizes, int n_in,
                              void* d_out, int out_size)
{
    const float* nf       = (const float*)d_in[0];
    const float* sh       = (const float*)d_in[1];
    const int*   senders  = (const int*)  d_in[2];
    const int*   recv     = (const int*)  d_in[3];
    const float* W0       = (const float*)d_in[4];
    const float* W1       = (const float*)d_in[5];
    const float* Ws0      = (const float*)d_in[6];
    const float* Ws1      = (const float*)d_in[7];
    float* out = (float*)d_out;

    int N = in_sizes[0] / 128;
    int E = in_sizes[2];

    k_fill<<<(E + 511) / 512, 512>>>(recv, senders, E);
    k_main<<<NBLK, 256>>>(nf, sh, W0, W1, Ws0, Ws1, out, N);
}

// round 16
// speedup vs baseline: 1.7633x; 1.0134x over previous
#include <cuda_runtime.h>
#include <cstdint>

// ============================================================================
// Layer_70411693850653 — equivariant GNN layer. (R15 + paired-column frags)
//
//  * messages[384:640] never consumed -> skipped
//  * agg == 1.5 * feats[:, :128] -> skip connection folded into weights
//  * scatter_mean via bucketed inverse-CSR + register gather (no float atomics)
//  * Phase B = tf32 mma.sync.m16n8k8; R16: columns permuted within each
//    8-wide k-block (c -> 2*(c&3) + (c>>2)) so fragment pairs (c0, c0+4) are
//    adjacent -> ONE LDS.64 per fragment pair (Phase B instrs 120 -> 72/warp)
//  * R16: FSP=104 (wide-bank bijection for LDS.64); scalar/z M-tiles share
//    one 8-row zero pad block -> sF 40 rows, smem 43.3KB, 5 blocks/SM kept
//  * Phase A: R15 depth-2 pipelined edge loop (MLP=2)
//  * NO cross-barrier prefetch (twice-measured regression)
// ============================================================================

#define N_MAX 50000
#define CAP   32
#define TILE  8
#define FSP   104        // stride words: 52%16==4 -> LDS.64 conflict-free
#define NBLK  740        // 5 per SM on 148 SMs

__device__ int  g_deg[N_MAX];            // zero-init at load; k_main resets
__device__ int2 g_bucket[N_MAX * CAP];   // {sender, edge}

// ---------------------------------------------------------------------------
__global__ void k_fill(const int* __restrict__ recv,
                       const int* __restrict__ senders, int E) {
    int e = blockIdx.x * blockDim.x + threadIdx.x;
    if (e < E) {
        int r = recv[e];
        int slot = atomicAdd(&g_deg[r], 1);
        if (slot < CAP) g_bucket[r * CAP + slot] = make_int2(senders[e], e);
    }
}

// ---------------------------------------------------------------------------
__device__ __forceinline__ uint32_t f2tf(float x) {
    uint32_t r;
    asm("cvt.rna.tf32.f32 %0, %1;" : "=r"(r) : "f"(x));
    return r;
}

__device__ __forceinline__ void mma_tf32(float c[4],
    uint32_t a0, uint32_t a1, uint32_t a2, uint32_t a3,
    uint32_t b0, uint32_t b1)
{
    asm volatile(
        "mma.sync.aligned.m16n8k8.row.col.f32.tf32.tf32.f32 "
        "{%0,%1,%2,%3}, {%4,%5,%6,%7}, {%8,%9}, {%0,%1,%2,%3};"
        : "+f"(c[0]), "+f"(c[1]), "+f"(c[2]), "+f"(c[3])
        : "r"(a0), "r"(a1), "r"(a2), "r"(a3), "r"(b0), "r"(b1));
}

// column permutation within each 8-wide k-block: c -> 2*(c&3) + (c>>2)
__device__ __forceinline__ int pcol(int c) {
    return (c & ~7) + 2 * (c & 3) + ((c >> 2) & 1);
}

// ---------------------------------------------------------------------------
// sF rows: 0-7 scalar | 8-15 x | 16-23 y | 24-31 z | 32-39 shared zero pad
__global__ void __launch_bounds__(256, 5) k_main(
    const float* __restrict__ nf, const float* __restrict__ sh,
    const float* __restrict__ W0, const float* __restrict__ W1,
    const float* __restrict__ Ws0, const float* __restrict__ Ws1,
    float* __restrict__ out, int N)
{
    __shared__ uint32_t sF [40 * FSP];       // tf32 feats rows   (16.6 KB)
    __shared__ uint32_t sW0[32 * FSP];       // Wt0[v][u] tf32    (13.3 KB)
    __shared__ uint32_t sW1[32 * FSP];       // Wt1[v][u] tf32    (13.3 KB)

    const float invA = 0.10206207261596575f;         // 1/sqrt(96)
    const float cB   = 1.5f * 0.17677669529663687f;  // 1.5/sqrt(32)
    const float INV_SQRT3 = 0.5773502691896258f;

    const int t    = threadIdx.x;
    const int w    = t >> 5;
    const int lane = t & 31;

    // ---- prologue: effective weights, transposed [v][u], permuted cols ----
    for (int i = t; i < 96 * 32; i += 256) {
        int u = i >> 5, v = i & 31;
        float w0 = W0[i] * invA;
        float w1 = W1[i] * invA;
        if (u < 32) { w0 = fmaf(cB, Ws0[i], w0); w1 = fmaf(cB, Ws1[i], w1); }
        int pc = pcol(u);
        sW0[v * FSP + pc] = f2tf(w0);
        sW1[v * FSP + pc] = f2tf(w1);
    }
    // zero the shared pad rows (32-39) once
    for (int i = t; i < 8 * FSP; i += 256)
        sF[32 * FSP + i] = 0;

    // fragment indices (loop-invariant)
    const int r0 = lane >> 2;   // 0..7
    const int c0 = lane & 3;    // 0..3
    // permuted column for Phase A stores (lane = logical column in segment)
    const int plane = (lane & 24) + 2 * (lane & 3) + ((lane >> 2) & 1);
    // Phase B role: warps 0..5 = (Mtile m, n-half nh); warps 6,7 idle in B
    const int m  = w >> 1;                  // 0=scalar, 1=x|y, 2=z
    const int nh = w & 1;
    const int nbase = nh * 16;
    const uint32_t* Wt = (m == 0) ? sW0 : sW1;
    const int loR = ((m == 0) ? 0 : (m == 1) ? 8 : 24) + r0;
    const int hiR = ((m == 1) ? 16 : 32) + r0;      // pad rows for m=0,2

    const int ntiles = (N + TILE - 1) / TILE;
    for (int tile = blockIdx.x; tile < ntiles; tile += gridDim.x) {
        __syncthreads();   // previous tile's Phase B readers done with sF

        // ---------------- Phase A: warp w owns node tile*8 + w -------------
        {
            const int n = tile * TILE + w;

            float a0 = 0.f, ax = 0.f, ay = 0.f, az = 0.f;
            float p00 = 0.f, dot = 0.f;
            float qx = 0.f, qy = 0.f, qz = 0.f;   // p01 = s0*f1
            float rx = 0.f, ry = 0.f, rz = 0.f;   // p10 = f0*s1

            int d = 0;
            if (n < N) d = g_deg[n];
            const int dc = min(d, CAP);
            if (n < N && lane == 0) g_deg[n] = 0;   // maintain zero-invariant

            int    my_s  = 0;
            float4 my_sh = make_float4(0.f, 0.f, 0.f, 0.f);
            if (lane < dc) {
                int2 se = g_bucket[n * CAP + lane];
                my_s    = se.x;
                my_sh   = *reinterpret_cast<const float4*>(sh + (size_t)se.y * 4);
            }

            if (dc > 0) {
                // ---- depth-2 pipelined edge loop (MLP=2) ----
                int s0i = __shfl_sync(0xffffffffu, my_s, 0);
                const float* row0 = nf + (size_t)s0i * 128;
                float f0 = row0[lane];
                float g0 = row0[32 + 3 * lane];
                float g1 = row0[33 + 3 * lane];
                float g2 = row0[34 + 3 * lane];

                for (int j = 0; j < dc; j++) {
                    float nf0 = 0.f, ng0 = 0.f, ng1 = 0.f, ng2 = 0.f;
                    if (j + 1 < dc) {
                        int sn = __shfl_sync(0xffffffffu, my_s, j + 1);
                        const float* rn = nf + (size_t)sn * 128;
                        nf0 = rn[lane];
                        ng0 = rn[32 + 3 * lane];
                        ng1 = rn[33 + 3 * lane];
                        ng2 = rn[34 + 3 * lane];
                    }
                    float s0  = __shfl_sync(0xffffffffu, my_sh.x, j);
                    float s1x = __shfl_sync(0xffffffffu, my_sh.y, j);
                    float s1y = __shfl_sync(0xffffffffu, my_sh.z, j);
                    float s1z = __shfl_sync(0xffffffffu, my_sh.w, j);

                    a0 += f0; ax += g0; ay += g1; az += g2;
                    p00 = fmaf(s0, f0, p00);
                    dot = fmaf(s1x, g0, fmaf(s1y, g1, fmaf(s1z, g2, dot)));
                    qx  = fmaf(s0, g0, qx);
                    qy  = fmaf(s0, g1, qy);
                    qz  = fmaf(s0, g2, qz);
                    rx  = fmaf(f0, s1x, rx);
                    ry  = fmaf(f0, s1y, ry);
                    rz  = fmaf(f0, s1z, rz);

                    f0 = nf0; g0 = ng0; g1 = ng1; g2 = ng2;
                }
            }

            const float scale = 1.0f / (1.5f * (float)max(d, 1));
            // scalar row w:   [a0, p00, dot];  x row 8+w;  y row 16+w;  z 24+w
            sF[ w       * FSP +      plane] = f2tf(a0 * scale);
            sF[ w       * FSP + 32 + plane] = f2tf(p00 * scale);
            sF[ w       * FSP + 64 + plane] = f2tf(dot * scale * INV_SQRT3);
            sF[( 8 + w) * FSP +      plane] = f2tf(ax * scale);
            sF[( 8 + w) * FSP + 32 + plane] = f2tf(qx * scale);
            sF[( 8 + w) * FSP + 64 + plane] = f2tf(rx * scale);
            sF[(16 + w) * FSP +      plane] = f2tf(ay * scale);
            sF[(16 + w) * FSP + 32 + plane] = f2tf(qy * scale);
            sF[(16 + w) * FSP + 64 + plane] = f2tf(ry * scale);
            sF[(24 + w) * FSP +      plane] = f2tf(az * scale);
            sF[(24 + w) * FSP + 32 + plane] = f2tf(qz * scale);
            sF[(24 + w) * FSP + 64 + plane] = f2tf(rz * scale);
        }
        __syncthreads();   // sF ready

        // ---------------- Phase B: tf32 MMA, warps 0..5, LDS.64 frags ------
        if (w < 6) {
            float c[2][4];
            #pragma unroll
            for (int nt = 0; nt < 2; nt++)
                #pragma unroll
                for (int i = 0; i < 4; i++) c[nt][i] = 0.f;

            #pragma unroll
            for (int k = 0; k < 12; k++) {
                const int kb = 8 * k + 2 * c0;
                uint2 alo = *reinterpret_cast<const uint2*>(&sF[loR * FSP + kb]);
                uint2 ahi = *reinterpret_cast<const uint2*>(&sF[hiR * FSP + kb]);
                #pragma unroll
                for (int nt = 0; nt < 2; nt++) {
                    uint2 b = *reinterpret_cast<const uint2*>(
                        &Wt[(nbase + nt * 8 + r0) * FSP + kb]);
                    mma_tf32(c[nt], alo.x, ahi.x, alo.y, ahi.y, b.x, b.y);
                }
            }

            // store: lo rows -> c[.][0..1], hi rows -> c[.][2..3]
            const int node = tile * TILE + r0;
            if (node < N) {
                float* o = out + (size_t)node * 128;
                #pragma unroll
                for (int nt = 0; nt < 2; nt++) {
                    int v0 = nbase + nt * 8 + 2 * c0;
                    if (m == 0) {            // scalar (lo only; hi = pad)
                        o[v0]     = c[nt][0];
                        o[v0 + 1] = c[nt][1];
                    } else if (m == 1) {     // lo = x, hi = y
                        o[32 + 3 * v0 + 0]       = c[nt][0];
                        o[32 + 3 * (v0 + 1) + 0] = c[nt][1];
                        o[32 + 3 * v0 + 1]       = c[nt][2];
                        o[32 + 3 * (v0 + 1) + 1] = c[nt][3];
                    } else {                 // lo = z (hi = pad)
                        o[32 + 3 * v0 + 2]       = c[nt][0];
                        o[32 + 3 * (v0 + 1) + 2] = c[nt][1];
                    }
                }
            }
        }
    }
}

// ---------------------------------------------------------------------------
extern "C" void kernel_launch(void* const* d_in, const int* in_sizes, int n_in,
                              void* d_out, int out_size)
{
    const float* nf       = (const float*)d_in[0];
    const float* sh       = (const float*)d_in[1];
    const int*   senders  = (const int*)  d_in[2];
    const int*   recv     = (const int*)  d_in[3];
    const float* W0       = (const float*)d_in[4];
    const float* W1       = (const float*)d_in[5];
    const float* Ws0      = (const float*)d_in[6];
    const float* Ws1      = (const float*)d_in[7];
    float* out = (float*)d_out;

    int N = in_sizes[0] / 128;
    int E = in_sizes[2];

    k_fill<<<(E + 511) / 512, 512>>>(recv, senders, E);
    k_main<<<NBLK, 256>>>(nf, sh, W0, W1, Ws0, Ws1, out, N);
}